// round 6
// baseline (speedup 1.0000x reference)
#include <cuda_runtime.h>
#include <math.h>

#define Bb 128
#define Tt 100
#define Dd 2048
#define Hh 1024
#define Oo 20
#define BH (Bb*Hh)          // 131072
#define TW 91               // T - WINDOW + 1

// ---------------- device scratch ----------
__device__ float g_A[Tt*BH];         // input projection G1, layout [t][b][h]
__device__ float g_S[Tt*BH];         // spike history [t][b*H+h]
__device__ float g_hmem[BH];
__device__ float g_omem[Bb*Oo];
__device__ float g_osum[Bb*Oo];
__device__ float g_nbr[Tt];

// ---------------- init -------------------------------------------------------
__global__ void k_init(const float* __restrict__ hm, const float* __restrict__ om) {
    int idx = blockIdx.x * blockDim.x + threadIdx.x;
    if (idx < BH)                        g_hmem[idx] = hm[idx];
    else if (idx < BH + Bb*Oo)           g_omem[idx - BH] = om[idx - BH];
    else if (idx < BH + 2*Bb*Oo)         g_osum[idx - BH - Bb*Oo] = 0.f;
    else if (idx < BH + 2*Bb*Oo + Tt)    g_nbr[idx - BH - 2*Bb*Oo] = 0.f;
}

// ---- ingemm tile: one 32(b) x 32(h) tile of slice t2, full K=2048 ----------
// Sequential ascending-k, single accumulator per element (bit-exact contract).
// 256 threads, 2x2 per thread, double-buffered BK=32.
__device__ __forceinline__ void ingemm_tile(
    const float* __restrict__ X, const float* __restrict__ W1,
    int t2, int bid,
    float (*As)[32][34], float (*Bs)[32][34])
{
    const int tid = threadIdx.x;
    const int b0 = (bid >> 5) * 32;          // 4 b-tiles
    const int h0 = (bid & 31) * 32;          // 32 h-tiles
    const int lr = tid >> 3;                 // 0..31
    const int lc = (tid & 7) << 2;           // 0,4,...,28
    const int txm = tid & 15, txn = tid >> 4;

    const float* pa = X + (size_t)(b0 + lr) * (Tt * Dd) + (size_t)t2 * Dd + lc;
    const float* pb = W1 + (size_t)(h0 + lr) * Dd + lc;

    float a00 = 0.f, a01 = 0.f, a10 = 0.f, a11 = 0.f;

    float4 ra = *(const float4*)pa;
    float4 rb = *(const float4*)pb;
#pragma unroll
    for (int j = 0; j < 4; j++) {
        As[0][lc + j][lr] = ((const float*)&ra)[j];
        Bs[0][lc + j][lr] = ((const float*)&rb)[j];
    }
    __syncthreads();

    const int NK = Dd / 32;   // 64
    int buf = 0;
    for (int kt = 0; kt < NK; ++kt) {
        if (kt + 1 < NK) {
            ra = *(const float4*)(pa + (kt + 1) * 32);
            rb = *(const float4*)(pb + (kt + 1) * 32);
        }
#pragma unroll
        for (int kk = 0; kk < 32; ++kk) {
            float2 a = *(const float2*)&As[buf][kk][txm * 2];
            float2 b = *(const float2*)&Bs[buf][kk][txn * 2];
            a00 = fmaf(a.x, b.x, a00);
            a01 = fmaf(a.x, b.y, a01);
            a10 = fmaf(a.y, b.x, a10);
            a11 = fmaf(a.y, b.y, a11);
        }
        if (kt + 1 < NK) {
            int nb = buf ^ 1;
#pragma unroll
            for (int j = 0; j < 4; j++) {
                As[nb][lc + j][lr] = ((const float*)&ra)[j];
                Bs[nb][lc + j][lr] = ((const float*)&rb)[j];
            }
        }
        buf ^= 1;
        __syncthreads();
    }

    int bm = b0 + txm * 2, n = h0 + txn * 2;
    float* dst = g_A + (size_t)t2 * BH;
    dst[(size_t)bm * Hh + n]           = a00;
    dst[(size_t)bm * Hh + n + 1]       = a01;
    dst[(size_t)(bm + 1) * Hh + n]     = a10;
    dst[(size_t)(bm + 1) * Hh + n + 1] = a11;
}

// ---------------- prologue: input slice 0 ----------------------------------
__global__ __launch_bounds__(256) void k_pre(
    const float* __restrict__ X, const float* __restrict__ W1)
{
    __shared__ float As[2][32][34];
    __shared__ float Bs[2][32][34];
    ingemm_tile(X, W1, 0, blockIdx.x, As, Bs);
}

// ---------------- fused step kernel ----------------------------------------
// grid 128 blocks x 256 threads. Each block serially:
//   phase O: output layer for step t-1 (b = blockIdx), exact R3 k_out logic
//   phase R: recur 32x32 tile for step t  + fused hidden membrane epilogue
//   phase I: input-GEMM tile for slice t+1
__global__ __launch_bounds__(256) void k_step(
    const float* __restrict__ X,  const float* __restrict__ W1,
    const float* __restrict__ hs0, const float* __restrict__ W,
    const float* __restrict__ b1, const float* __restrict__ b2,
    const float* __restrict__ thr_h,
    const float* __restrict__ W2, const float* __restrict__ b2o,
    const float* __restrict__ thr_o, int t)
{
    __shared__ float As[2][32][34];
    __shared__ float Bs[2][32][34];
    __shared__ float rs[Oo][128];
    __shared__ float spsm[Oo];
    __shared__ float red[256];

    const int tid = threadIdx.x;
    const int bid = blockIdx.x;

    // ---------- phase O: output layer for t-1 ----------
    if (t > 0) {
        int b = bid;
        const float* hs = g_S + (size_t)(t - 1) * BH + (size_t)b * Hh;
        float acc[Oo];
#pragma unroll
        for (int o = 0; o < Oo; o++) acc[o] = 0.f;
        if (tid < 128) {
            for (int k = tid; k < Hh; k += 128) {
                float h = hs[k];
#pragma unroll
                for (int o = 0; o < Oo; o++) acc[o] = fmaf(h, W2[o * Hh + k], acc[o]);
            }
#pragma unroll
            for (int o = 0; o < Oo; o++) rs[o][tid] = acc[o];
        }
        __syncthreads();
        for (int s = 64; s > 0; s >>= 1) {
            if (tid < s)
#pragma unroll
                for (int o = 0; o < Oo; o++) rs[o][tid] += rs[o][tid + s];
            __syncthreads();
        }
        if (tid < Oo) {
            int o = tid;
            float m = g_omem[b * Oo + o] + (rs[o][0] + b2o[o]);
            float th = thr_o[o];
            float sp = (m - th > 0.f) ? 1.f : 0.f;
            m = m * (1.f - sp);
            float neg = (m < -th) ? 1.f : 0.f;
            m = m * (1.f - neg) - th * neg;
            g_omem[b * Oo + o] = m;
            g_osum[b * Oo + o] += sp;
            spsm[o] = sp;
        }
        __syncthreads();
        if (tid == 0) {
            float s = 0.f;
            for (int o = 0; o < Oo; o++) s += spsm[o];
            atomicAdd(&g_nbr[t - 1], s * (1.f / Bb));
        }
        __syncthreads();
    }

    // ---------- phase R: recurrent GEMM tile + hidden membrane ----------
    {
        const int m0 = (bid >> 5) * 32;      // 4 m-tiles (batch)
        const int n0 = (bid & 31) * 32;      // 32 n-tiles (hidden)
        const int lr = tid >> 3;
        const int lc = (tid & 7) << 2;
        const int txm = tid & 15, txn = tid >> 4;

        const float* Amat = (t == 0) ? hs0 : (g_S + (size_t)(t - 1) * BH);
        const float* pa = Amat + (size_t)(m0 + lr) * Hh + lc;
        const float* pb = W + (size_t)(n0 + lr) * Hh + lc;

        float a00 = 0.f, a01 = 0.f, a10 = 0.f, a11 = 0.f;

        float4 ra = *(const float4*)pa;
        float4 rb = *(const float4*)pb;
#pragma unroll
        for (int j = 0; j < 4; j++) {
            As[0][lc + j][lr] = ((const float*)&ra)[j];
            Bs[0][lc + j][lr] = ((const float*)&rb)[j];
        }
        __syncthreads();

        const int NK = Hh / 32;   // 32
        int buf = 0;
        for (int kt = 0; kt < NK; ++kt) {
            if (kt + 1 < NK) {
                ra = *(const float4*)(pa + (kt + 1) * 32);
                rb = *(const float4*)(pb + (kt + 1) * 32);
            }
#pragma unroll
            for (int kk = 0; kk < 32; ++kk) {
                float2 a = *(const float2*)&As[buf][kk][txm * 2];
                float2 b = *(const float2*)&Bs[buf][kk][txn * 2];
                a00 = fmaf(a.x, b.x, a00);
                a01 = fmaf(a.x, b.y, a01);
                a10 = fmaf(a.y, b.x, a10);
                a11 = fmaf(a.y, b.y, a11);
            }
            if (kt + 1 < NK) {
                int nb = buf ^ 1;
#pragma unroll
                for (int j = 0; j < 4; j++) {
                    As[nb][lc + j][lr] = ((const float*)&ra)[j];
                    Bs[nb][lc + j][lr] = ((const float*)&rb)[j];
                }
            }
            buf ^= 1;
            __syncthreads();
        }

        // fused hidden membrane update for this block's 4 elements
        const int m = m0 + txm * 2, n = n0 + txn * 2;
        float accs[4] = {a00, a01, a10, a11};
        float spsum = 0.f;
        const float* gA = g_A + (size_t)t * BH;
#pragma unroll
        for (int e = 0; e < 4; e++) {
            int mm = m + (e >> 1);
            int nn = n + (e & 1);
            int bh = mm * Hh + nn;
            float G1 = gA[bh];
            float v = ((G1 + b1[nn]) + accs[e]) + b2[nn];
            float mem = g_hmem[bh] + v;
            float th = thr_h[nn];
            float sp = (mem - th > 0.f) ? 1.f : 0.f;
            mem = mem * (1.f - sp);
            float neg = (mem < -th) ? 1.f : 0.f;
            mem = mem * (1.f - neg) - th * neg;
            g_hmem[bh] = mem;
            g_S[(size_t)t * BH + bh] = sp;
            spsum += sp;
        }
        red[tid] = spsum;
        __syncthreads();
        for (int s = 128; s > 0; s >>= 1) {
            if (tid < s) red[tid] += red[tid + s];
            __syncthreads();
        }
        if (tid == 0) atomicAdd(&g_nbr[t], red[0] * (1.f / Bb));
        __syncthreads();
    }

    // ---------- phase I: input-GEMM slice t+1 ----------
    if (t + 1 < Tt) {
        ingemm_tile(X, W1, t + 1, bid, As, Bs);
    }
}

// ---------------- final output-layer step (t = Tt-1) ------------------------
__global__ __launch_bounds__(128) void k_out99(const float* __restrict__ W2,
    const float* __restrict__ b2o, const float* __restrict__ thr_o)
{
    __shared__ float rs[Oo][128];
    __shared__ float spsm[Oo];
    const int t = Tt - 1;
    int b = blockIdx.x, tid = threadIdx.x;
    const float* hs = g_S + (size_t)t * BH + (size_t)b * Hh;
    float acc[Oo];
#pragma unroll
    for (int o = 0; o < Oo; o++) acc[o] = 0.f;
    for (int k = tid; k < Hh; k += 128) {
        float h = hs[k];
#pragma unroll
        for (int o = 0; o < Oo; o++) acc[o] = fmaf(h, W2[o * Hh + k], acc[o]);
    }
#pragma unroll
    for (int o = 0; o < Oo; o++) rs[o][tid] = acc[o];
    __syncthreads();
    for (int s = 64; s > 0; s >>= 1) {
        if (tid < s)
#pragma unroll
            for (int o = 0; o < Oo; o++) rs[o][tid] += rs[o][tid + s];
        __syncthreads();
    }
    if (tid < Oo) {
        int o = tid;
        float m = g_omem[b * Oo + o] + (rs[o][0] + b2o[o]);
        float th = thr_o[o];
        float sp = (m - th > 0.f) ? 1.f : 0.f;
        m = m * (1.f - sp);
        float neg = (m < -th) ? 1.f : 0.f;
        m = m * (1.f - neg) - th * neg;
        g_omem[b * Oo + o] = m;
        g_osum[b * Oo + o] += sp;
        spsm[o] = sp;
    }
    __syncthreads();
    if (tid == 0) {
        float s = 0.f;
        for (int o = 0; o < Oo; o++) s += spsm[o];
        atomicAdd(&g_nbr[t], s * (1.f / Bb));
    }
}

// ---------------- sliding-window filter ------------------------------------
__global__ __launch_bounds__(128) void k_filt(float* __restrict__ out) {
    __shared__ float sm[128 * TW];
    int bh = blockIdx.x * 128 + threadIdx.x;
    const float* S = g_S + bh;
    float s = 0.f;
#pragma unroll
    for (int tt = 0; tt < 10; ++tt) s += S[(size_t)tt * BH];
    sm[threadIdx.x * TW + 0] = s / 10.0f;
    for (int tt = 10; tt < Tt; ++tt) {
        s += S[(size_t)tt * BH] - S[(size_t)(tt - 10) * BH];
        sm[threadIdx.x * TW + (tt - 9)] = s / 10.0f;
    }
    __syncthreads();
    float* dst = out + 229 + (size_t)blockIdx.x * 128 * TW;
    for (int idx = threadIdx.x; idx < 128 * TW; idx += 128) dst[idx] = sm[idx];
}

// ---------------- predictions / loss / nbr_events --------------------------
__global__ void k_final(const int* __restrict__ labels, float* __restrict__ out) {
    int tid = threadIdx.x;  // 256 threads
    __shared__ float red[128];
    if (tid < 128) {
        int b = tid;
        float mx = g_osum[b * Oo];
        int arg = 0;
        for (int o = 1; o < Oo; o++) {
            float v = g_osum[b * Oo + o];
            if (v > mx) { mx = v; arg = o; }
        }
        float se = 0.f;
        for (int o = 0; o < Oo; o++) se += expf(g_osum[b * Oo + o] - mx);
        float lse = mx + logf(se);
        out[b] = (float)arg;
        int lab = labels[b];
        red[b] = -(g_osum[b * Oo + lab] - lse);
    }
    __syncthreads();
    for (int s = 64; s > 0; s >>= 1) {
        if (tid < s) red[tid] += red[tid + s];
        __syncthreads();
    }
    if (tid == 0) out[128] = red[0] / (float)Bb;
    if (tid >= 128 && tid < 128 + Tt) out[129 + (tid - 128)] = g_nbr[tid - 128];
}

// ---------------- launcher --------------------------------------------------
extern "C" void kernel_launch(void* const* d_in, const int* in_sizes, int n_in,
                              void* d_out, int out_size) {
    const float* input = (const float*)d_in[0];
    const int*   labels = (const int*)d_in[1];
    const float* hmem0 = (const float*)d_in[2];
    const float* hspk0 = (const float*)d_in[3];
    const float* omem0 = (const float*)d_in[4];
    const float* Wi2h  = (const float*)d_in[6];
    const float* bi2h  = (const float*)d_in[7];
    const float* Wh2h  = (const float*)d_in[8];
    const float* bh2h  = (const float*)d_in[9];
    const float* Wh2o  = (const float*)d_in[10];
    const float* bh2o  = (const float*)d_in[11];
    const float* thr_h = (const float*)d_in[12];
    const float* thr_o = (const float*)d_in[13];
    float* out = (float*)d_out;

    int initN = BH + 2 * Bb * Oo + Tt;
    k_init<<<(initN + 255) / 256, 256>>>(hmem0, omem0);
    k_pre<<<128, 256>>>(input, Wi2h);
    for (int t = 0; t < Tt; ++t) {
        k_step<<<128, 256>>>(input, Wi2h, hspk0, Wh2h, bi2h, bh2h, thr_h,
                             Wh2o, bh2o, thr_o, t);
    }
    k_out99<<<Bb, 128>>>(Wh2o, bh2o, thr_o);
    k_filt<<<BH / 128, 128>>>(out);
    k_final<<<1, 256>>>(labels, out);
}